// round 3
// baseline (speedup 1.0000x reference)
#include <cuda_runtime.h>

#define B_    32
#define CIN   512
#define CI    256
#define NPIX  3136
#define EPSV  1e-5f

// ---------------- scratch (static device globals; no allocation) ----------------
__device__ float d_TPG[(size_t)B_ * 3 * CI * NPIX];   // [b][768][3136]: theta|phi|g
__device__ float d_F  [(size_t)B_ * CI * CI];         // [b][256][256]
__device__ float d_Y  [(size_t)B_ * CI * NPIX];       // [b][256][3136]
__device__ float d_Wcat[3 * CI * CIN];                // theta_w | phi_w | g_w
__device__ float d_Bcat[3 * CI];
__device__ float d_Sum[CIN];
__device__ float d_Sq [CIN];
__device__ float d_Scale[CIN];
__device__ float d_Shift[CIN];

// ---------------- prep: concat weights/biases, zero BN stats ----------------
__global__ void prep_k(const float* __restrict__ gw, const float* __restrict__ gb,
                       const float* __restrict__ tw, const float* __restrict__ tb,
                       const float* __restrict__ pw, const float* __restrict__ pb)
{
    int i = blockIdx.x * 256 + threadIdx.x;
    const int per = CI * CIN;  // 131072
    if (i < 3 * per) {
        int m = i / per, off = i - m * per;
        d_Wcat[i] = (m == 0 ? tw : (m == 1 ? pw : gw))[off];
    }
    if (i < CI)            d_Bcat[i] = tb[i];
    else if (i < 2 * CI)   d_Bcat[i] = pb[i - CI];
    else if (i < 3 * CI)   d_Bcat[i] = gb[i - 2 * CI];
    if (i < CIN) { d_Sum[i] = 0.f; d_Sq[i] = 0.f; }
}

// ---------------- generic tiled SGEMM: C = alpha*A@B(+bias)(+res), opt BN stats ----
// BM=BN=128, BK=8, 256 threads, 8x8 microtile (4+4 split pattern).
// M must be a multiple of 128; K a multiple of 8; N guarded (multiple of 4).
template<bool TRANS_B, bool HAS_BIAS, bool HAS_RES, bool DO_STATS>
__global__ __launch_bounds__(256, 2)
void sgemm_k(int M, int N, int K, float alpha,
             const float* __restrict__ A,  int lda, long long sA,
             const float* __restrict__ Bm, int ldb, long long sB,
             float* __restrict__ C,        int ldc, long long sC,
             const float* __restrict__ bias,
             const float* __restrict__ res, long long sR)
{
    __shared__ float As[8][128];
    __shared__ float Bs[8][128];
    __shared__ float sSum[128];
    __shared__ float sSq [128];

    const int t  = threadIdx.x;
    const int bz = blockIdx.z;
    A  += (long long)bz * sA;
    Bm += (long long)bz * sB;
    C  += (long long)bz * sC;

    const int rowA = blockIdx.y * 128;
    const int colB = blockIdx.x * 128;

    const int tidx = t & 15;        // N dir
    const int tidy = t >> 4;        // M dir

    float acc[8][8];
    #pragma unroll
    for (int i = 0; i < 8; i++)
        #pragma unroll
        for (int j = 0; j < 8; j++) acc[i][j] = 0.f;

    const int aRow = t >> 1;
    const int aK   = (t & 1) << 2;
    const float* aPtr = A + (long long)(rowA + aRow) * lda + aK;

    for (int k0 = 0; k0 < K; k0 += 8) {
        // ---- A tile (row-major [M,K]) ----
        float4 av = *(const float4*)(aPtr + k0);
        As[aK + 0][aRow] = av.x; As[aK + 1][aRow] = av.y;
        As[aK + 2][aRow] = av.z; As[aK + 3][aRow] = av.w;

        // ---- B tile ----
        if (!TRANS_B) {
            int bk = t >> 5;            // 0..7
            int bc = (t & 31) << 2;     // 0..124
            float4 bv;
            if (colB + bc < N)
                bv = *(const float4*)(Bm + (long long)(k0 + bk) * ldb + colB + bc);
            else
                bv = make_float4(0.f, 0.f, 0.f, 0.f);
            *(float4*)&Bs[bk][bc] = bv;
        } else {
            // B stored [N,K] row-major; out(i,j) = sum_k A(i,k)*B(j,k)
            int bc = t >> 1;            // 0..127
            int bk = (t & 1) << 2;
            float4 bv;
            if (colB + bc < N)
                bv = *(const float4*)(Bm + (long long)(colB + bc) * ldb + k0 + bk);
            else
                bv = make_float4(0.f, 0.f, 0.f, 0.f);
            Bs[bk + 0][bc] = bv.x; Bs[bk + 1][bc] = bv.y;
            Bs[bk + 2][bc] = bv.z; Bs[bk + 3][bc] = bv.w;
        }
        __syncthreads();

        #pragma unroll
        for (int k = 0; k < 8; k++) {
            float4 a0 = *(const float4*)&As[k][tidy << 2];
            float4 a1 = *(const float4*)&As[k][64 + (tidy << 2)];
            float4 b0 = *(const float4*)&Bs[k][tidx << 2];
            float4 b1 = *(const float4*)&Bs[k][64 + (tidx << 2)];
            float ar[8] = {a0.x, a0.y, a0.z, a0.w, a1.x, a1.y, a1.z, a1.w};
            float br[8] = {b0.x, b0.y, b0.z, b0.w, b1.x, b1.y, b1.z, b1.w};
            #pragma unroll
            for (int i = 0; i < 8; i++)
                #pragma unroll
                for (int j = 0; j < 8; j++)
                    acc[i][j] = fmaf(ar[i], br[j], acc[i][j]);
        }
        __syncthreads();
    }

    if (DO_STATS) {
        if (t < 128) { sSum[t] = 0.f; sSq[t] = 0.f; }
        __syncthreads();
    }

    const float* R = HAS_RES ? (res + (long long)bz * sR) : nullptr;
    const int gc0 = colB + (tidx << 2);
    const int gc1 = colB + 64 + (tidx << 2);

    #pragma unroll
    for (int i = 0; i < 8; i++) {
        int ri = (i < 4) ? ((tidy << 2) + i) : (64 + (tidy << 2) + i - 4);
        int gr = rowA + ri;
        float bv = HAS_BIAS ? bias[gr] : 0.f;
        float* crow = C + (long long)gr * ldc;
        const float* rrow = HAS_RES ? (R + (long long)gr * ldc) : nullptr;

        float ls = 0.f, lq = 0.f;

        if (gc0 < N) {
            float4 v;
            v.x = acc[i][0] * alpha + bv;
            v.y = acc[i][1] * alpha + bv;
            v.z = acc[i][2] * alpha + bv;
            v.w = acc[i][3] * alpha + bv;
            if (HAS_RES) {
                float4 r = *(const float4*)(rrow + gc0);
                v.x += r.x; v.y += r.y; v.z += r.z; v.w += r.w;
            }
            *(float4*)(crow + gc0) = v;
            if (DO_STATS) {
                ls += v.x + v.y + v.z + v.w;
                lq += v.x * v.x + v.y * v.y + v.z * v.z + v.w * v.w;
            }
        }
        if (gc1 < N) {
            float4 v;
            v.x = acc[i][4] * alpha + bv;
            v.y = acc[i][5] * alpha + bv;
            v.z = acc[i][6] * alpha + bv;
            v.w = acc[i][7] * alpha + bv;
            if (HAS_RES) {
                float4 r = *(const float4*)(rrow + gc1);
                v.x += r.x; v.y += r.y; v.z += r.z; v.w += r.w;
            }
            *(float4*)(crow + gc1) = v;
            if (DO_STATS) {
                ls += v.x + v.y + v.z + v.w;
                lq += v.x * v.x + v.y * v.y + v.z * v.z + v.w * v.w;
            }
        }
        if (DO_STATS) { atomicAdd(&sSum[ri], ls); atomicAdd(&sSq[ri], lq); }
    }

    if (DO_STATS) {
        __syncthreads();
        if (t < 128) {
            atomicAdd(&d_Sum[rowA + t], sSum[t]);
            atomicAdd(&d_Sq [rowA + t], sSq [t]);
        }
    }
}

// ---------------- BN finalize: per-channel scale/shift ----------------
__global__ void finalize_k(const float* __restrict__ gamma, const float* __restrict__ beta)
{
    int c = threadIdx.x;
    if (c < CIN) {
        const float cnt = (float)((long long)B_ * NPIX);
        float mean = d_Sum[c] / cnt;
        float var  = d_Sq[c] / cnt - mean * mean;
        float s = gamma[c] * rsqrtf(var + EPSV);
        d_Scale[c] = s;
        d_Shift[c] = beta[c] - mean * s;
    }
}

// ---------------- BN apply in-place on d_out ----------------
__global__ void apply_k(float* __restrict__ out)
{
    const long long n4 = (long long)B_ * CIN * NPIX / 4;
    const long long stride = (long long)gridDim.x * blockDim.x;
    for (long long i = (long long)blockIdx.x * blockDim.x + threadIdx.x; i < n4; i += stride) {
        int c = (int)((i / (NPIX / 4)) % CIN);
        float s = d_Scale[c], sh = d_Shift[c];
        float4 v = ((float4*)out)[i];
        v.x = v.x * s + sh; v.y = v.y * s + sh;
        v.z = v.z * s + sh; v.w = v.w * s + sh;
        ((float4*)out)[i] = v;
    }
}

// ---------------- launch ----------------
extern "C" void kernel_launch(void* const* d_in, const int* in_sizes, int n_in,
                              void* d_out, int out_size)
{
    const float* x       = (const float*)d_in[0];
    const float* g_w     = (const float*)d_in[1];
    const float* g_b     = (const float*)d_in[2];
    const float* theta_w = (const float*)d_in[3];
    const float* theta_b = (const float*)d_in[4];
    const float* phi_w   = (const float*)d_in[5];
    const float* phi_b   = (const float*)d_in[6];
    const float* W_w     = (const float*)d_in[7];
    const float* W_b     = (const float*)d_in[8];
    const float* gamma   = (const float*)d_in[9];
    const float* beta    = (const float*)d_in[10];
    float* out = (float*)d_out;

    float *tpg, *fbuf, *ybuf;
    cudaGetSymbolAddress((void**)&tpg,  d_TPG);
    cudaGetSymbolAddress((void**)&fbuf, d_F);
    cudaGetSymbolAddress((void**)&ybuf, d_Y);
    float *wcat, *bcat;
    cudaGetSymbolAddress((void**)&wcat, d_Wcat);
    cudaGetSymbolAddress((void**)&bcat, d_Bcat);

    const long long sX   = (long long)CIN * NPIX;        // 1605632
    const long long sTPG = (long long)3 * CI * NPIX;     // 2408448
    const long long sF   = (long long)CI * CI;           // 65536
    const long long sY   = (long long)CI * NPIX;         // 802816
    const int nBlk = (NPIX + 127) / 128;                 // 25

    // 0) prep: concat weights, zero stats
    prep_k<<<(3 * CI * CIN + 255) / 256, 256>>>(g_w, g_b, theta_w, theta_b, phi_w, phi_b);

    // 1) theta/phi/g fused conv: [768,3136] = Wcat[768,512] @ x[b][512,3136] + Bcat
    sgemm_k<false, true, false, false><<<dim3(nBlk, 6, B_), 256>>>(
        3 * CI, NPIX, CIN, 1.f,
        wcat, CIN, 0,
        x, NPIX, sX,
        tpg, NPIX, sTPG,
        bcat, nullptr, 0);

    // 2) gram: f = theta @ phi^T / N   (TRANS_B: both K-contiguous)
    sgemm_k<true, false, false, false><<<dim3(2, 2, B_), 256>>>(
        CI, CI, NPIX, 1.f / (float)NPIX,
        tpg, NPIX, sTPG,                      // theta rows [0,256)
        tpg + (long long)CI * NPIX, NPIX, sTPG, // phi rows [256,512)
        fbuf, CI, sF,
        nullptr, nullptr, 0);

    // 3) y = f @ g
    sgemm_k<false, false, false, false><<<dim3(nBlk, 2, B_), 256>>>(
        CI, NPIX, CI, 1.f,
        fbuf, CI, sF,
        tpg + (long long)2 * CI * NPIX, NPIX, sTPG, // g rows [512,768)
        ybuf, NPIX, sY,
        nullptr, nullptr, 0);

    // 4) z = W_w @ y + W_b + x  -> d_out, fused BN stats
    sgemm_k<false, true, true, true><<<dim3(nBlk, 4, B_), 256>>>(
        CIN, NPIX, CI, 1.f,
        W_w, CI, 0,
        ybuf, NPIX, sY,
        out, NPIX, sX,
        W_b, x, sX);

    // 5) BN finalize + apply
    finalize_k<<<1, 512>>>(gamma, beta);
    apply_k<<<1184, 256>>>(out);
}

// round 5
// speedup vs baseline: 1.8972x; 1.8972x over previous
#include <cuda_runtime.h>
#include <cstdint>

#define B_    32
#define CIN   512
#define CI    256
#define NPIX  3136
#define EPSV  1e-5f

// ---------------- scratch (static device globals; no allocation) ----------------
__device__ float d_TPG[(size_t)B_ * 3 * CI * NPIX];   // [b][768][3136]: theta|phi|g
__device__ float d_F  [(size_t)B_ * CI * CI];         // [b][256][256]
__device__ float d_Y  [(size_t)B_ * CI * NPIX];       // [b][256][3136]
__device__ float d_Wcat[3 * CI * CIN];
__device__ float d_Bcat[3 * CI];
__device__ float d_Sum[CIN];
__device__ float d_Sq [CIN];
__device__ float d_Scale[CIN];
__device__ float d_Shift[CIN];

// ================= PTX helpers (all sm_80+-portable; NO tcgen05) =================
__device__ __forceinline__ uint32_t smem_u32(const void* p) {
    uint32_t a;
    asm("{ .reg .u64 t; cvta.to.shared.u64 t, %1; cvt.u32.u64 %0, t; }" : "=r"(a) : "l"(p));
    return a;
}
__device__ __forceinline__ void cp16(uint32_t d, const void* s, bool ok) {
    int sz = ok ? 16 : 0;
    asm volatile("cp.async.cg.shared.global [%0], [%1], 16, %2;" :: "r"(d), "l"(s), "r"(sz) : "memory");
}
__device__ __forceinline__ void cp_commit() { asm volatile("cp.async.commit_group;" ::: "memory"); }
__device__ __forceinline__ void cp_wait0()  { asm volatile("cp.async.wait_group 0;" ::: "memory"); }
__device__ __forceinline__ uint32_t f2tf(float f) {
    uint32_t u;
    asm("cvt.rna.tf32.f32 %0, %1;" : "=r"(u) : "f"(f));
    return u;
}
__device__ __forceinline__ void mma8(float* c, const uint32_t* a, const uint32_t* b) {
    asm volatile(
        "mma.sync.aligned.m16n8k8.row.col.f32.tf32.tf32.f32 "
        "{%0,%1,%2,%3}, {%4,%5,%6,%7}, {%8,%9}, {%0,%1,%2,%3};"
        : "+f"(c[0]), "+f"(c[1]), "+f"(c[2]), "+f"(c[3])
        : "r"(a[0]), "r"(a[1]), "r"(a[2]), "r"(a[3]), "r"(b[0]), "r"(b[1]));
}

// ---------------- prep ----------------
__global__ void prep_k(const float* __restrict__ gw, const float* __restrict__ gb,
                       const float* __restrict__ tw, const float* __restrict__ tb,
                       const float* __restrict__ pw, const float* __restrict__ pb)
{
    int i = blockIdx.x * 256 + threadIdx.x;
    const int per = CI * CIN;
    if (i < 3 * per) {
        int m = i / per, off = i - m * per;
        d_Wcat[i] = (m == 0 ? tw : (m == 1 ? pw : gw))[off];
    }
    if (i < CI)            d_Bcat[i] = tb[i];
    else if (i < 2 * CI)   d_Bcat[i] = pb[i - CI];
    else if (i < 3 * CI)   d_Bcat[i] = gb[i - 2 * CI];
    if (i < CIN) { d_Sum[i] = 0.f; d_Sq[i] = 0.f; }
}

// ================= tf32 mma.sync GEMM =================
// D[M,Npix] = alpha*A@op(B) (+bias)(+res), fp32 accum.
// A: [M,K] K-contig.  B: TRANS_B ? [Npix,K] K-contig (out=A@B^T) : [K,Npix] pix-contig.
// Block 128x128, 128 threads (4 warps, 64x64 warp tiles), KTILE=32, double-buffered.
// Smem layout (uint32): per stage [A: 32x132][B: 32x132]; stage stride 8448.
template<bool TRANS_B, bool HAS_BIAS, bool HAS_RES, bool DO_STATS>
__global__ void __launch_bounds__(128, 1) mma_gemm(
    int Npix, int KT, float alpha,
    const float* __restrict__ A,  int lda, long long sA,
    const float* __restrict__ Bm, int ldb, long long sB,
    float* __restrict__ C,        int ldc, long long sC,
    const float* __restrict__ bias,
    const float* __restrict__ res, long long sR)
{
    extern __shared__ uint32_t sm[];
    const uint32_t smb = smem_u32(sm);
    const int tid = threadIdx.x;
    const int bz = blockIdx.z;
    A  += (long long)bz * sA;
    Bm += (long long)bz * sB;
    C  += (long long)bz * sC;
    const int rowA = blockIdx.y * 128;
    const int colB = blockIdx.x * 128;
    const int warp = tid >> 5, lane = tid & 31;
    const int wr = warp >> 1, wc = warp & 1;      // 2x2 warp grid
    const int g = lane >> 2, q = lane & 3;

    float acc[4][8][4];
    #pragma unroll
    for (int i = 0; i < 4; i++)
        #pragma unroll
        for (int j = 0; j < 8; j++)
            #pragma unroll
            for (int k = 0; k < 4; k++) acc[i][j][k] = 0.f;

    float4 ra[8];            // A staging (thread tid = row)
    float4 rb[8];            // B staging (TRANS_B only)

    auto ldgA = [&](int kt) {
        const float* p = A + (long long)(rowA + tid) * lda + kt * 32;
        #pragma unroll
        for (int j = 0; j < 8; j++) ra[j] = *(const float4*)(p + j * 4);
    };
    auto stsA = [&](int s) {
        uint32_t* dst = sm + s * 8448;           // A[k][m], stride 132
        #pragma unroll
        for (int j = 0; j < 8; j++) {
            dst[(4 * j + 0) * 132 + tid] = f2tf(ra[j].x);
            dst[(4 * j + 1) * 132 + tid] = f2tf(ra[j].y);
            dst[(4 * j + 2) * 132 + tid] = f2tf(ra[j].z);
            dst[(4 * j + 3) * 132 + tid] = f2tf(ra[j].w);
        }
    };
    auto ldgBT = [&](int kt) {                   // B [Npix,K] -> rows by tid
        const float* p = Bm + (long long)(colB + tid) * ldb + kt * 32;
        #pragma unroll
        for (int j = 0; j < 8; j++) rb[j] = *(const float4*)(p + j * 4);
    };
    auto stsBT = [&](int s) {
        uint32_t* dst = sm + s * 8448 + 4224;    // B[k][n], stride 132
        #pragma unroll
        for (int j = 0; j < 8; j++) {
            dst[(4 * j + 0) * 132 + tid] = f2tf(rb[j].x);
            dst[(4 * j + 1) * 132 + tid] = f2tf(rb[j].y);
            dst[(4 * j + 2) * 132 + tid] = f2tf(rb[j].z);
            dst[(4 * j + 3) * 132 + tid] = f2tf(rb[j].w);
        }
    };
    auto cpB = [&](int s, int kt) {              // B [K,Npix] direct copy (raw fp32)
        #pragma unroll
        for (int j = 0; j < 8; j++) {
            int u = tid + j * 128;
            int k = u >> 5, n16 = u & 31;
            int col = colB + n16 * 4;
            bool ok = col < Npix;
            uint32_t dst = smb + (s * 8448 + 4224 + k * 132 + n16 * 4) * 4;
            cp16(dst, Bm + (long long)(kt * 32 + k) * ldb + (ok ? col : 0), ok);
        }
        cp_commit();
    };

    auto compute = [&](int s) {
        const uint32_t* As_ = sm + s * 8448;
        const uint32_t* Bs_ = As_ + 4224;
        #pragma unroll
        for (int k8 = 0; k8 < 4; k8++) {
            const int kb = k8 * 8;
            uint32_t af[4][4], bf[8][2];
            #pragma unroll
            for (int mt = 0; mt < 4; mt++) {
                int m0 = wr * 64 + mt * 16 + g;
                af[mt][0] = As_[(kb + q) * 132 + m0];
                af[mt][1] = As_[(kb + q) * 132 + m0 + 8];
                af[mt][2] = As_[(kb + q + 4) * 132 + m0];
                af[mt][3] = As_[(kb + q + 4) * 132 + m0 + 8];
            }
            #pragma unroll
            for (int nt = 0; nt < 8; nt++) {
                int n0 = wc * 64 + nt * 8 + g;
                uint32_t b0 = Bs_[(kb + q) * 132 + n0];
                uint32_t b1 = Bs_[(kb + q + 4) * 132 + n0];
                if (!TRANS_B) {                  // cp.async path stored raw fp32
                    b0 = f2tf(__uint_as_float(b0));
                    b1 = f2tf(__uint_as_float(b1));
                }
                bf[nt][0] = b0; bf[nt][1] = b1;
            }
            #pragma unroll
            for (int mt = 0; mt < 4; mt++)
                #pragma unroll
                for (int nt = 0; nt < 8; nt++)
                    mma8(acc[mt][nt], af[mt], bf[nt]);
        }
    };

    // prologue: tile 0 -> stage 0
    ldgA(0);
    if (TRANS_B) ldgBT(0); else cpB(0, 0);
    stsA(0);
    if (TRANS_B) stsBT(0); else cp_wait0();
    __syncthreads();

    for (int kt = 0; kt < KT; kt++) {
        const int s = kt & 1, ns = s ^ 1;
        const bool more = (kt + 1 < KT);
        if (more) {
            ldgA(kt + 1);
            if (TRANS_B) ldgBT(kt + 1); else cpB(ns, kt + 1);
        }
        compute(s);
        if (more) {
            stsA(ns);
            if (TRANS_B) stsBT(ns); else cp_wait0();
        }
        __syncthreads();
    }

    // ---------------- epilogue ----------------
    float sumr[8], sqr[8];
    if (DO_STATS)
        #pragma unroll
        for (int i = 0; i < 8; i++) { sumr[i] = 0.f; sqr[i] = 0.f; }

    #pragma unroll
    for (int mt = 0; mt < 4; mt++) {
        const int r0 = rowA + wr * 64 + mt * 16 + g;
        const int r1 = r0 + 8;
        const float bv0 = HAS_BIAS ? bias[r0] : 0.f;
        const float bv1 = HAS_BIAS ? bias[r1] : 0.f;
        float* c0p = C + (long long)r0 * ldc;
        float* c1p = C + (long long)r1 * ldc;
        const float* rr0 = HAS_RES ? (res + (long long)bz * sR + (long long)r0 * ldc) : nullptr;
        const float* rr1 = HAS_RES ? (res + (long long)bz * sR + (long long)r1 * ldc) : nullptr;
        #pragma unroll
        for (int nt = 0; nt < 8; nt++) {
            const int col = colB + wc * 64 + nt * 8 + q * 2;
            if (col < Npix) {
                float v0 = acc[mt][nt][0] * alpha + bv0;
                float v1 = acc[mt][nt][1] * alpha + bv0;
                float v2 = acc[mt][nt][2] * alpha + bv1;
                float v3 = acc[mt][nt][3] * alpha + bv1;
                if (HAS_RES) {
                    float2 e0 = *(const float2*)(rr0 + col);
                    float2 e1 = *(const float2*)(rr1 + col);
                    v0 += e0.x; v1 += e0.y; v2 += e1.x; v3 += e1.y;
                }
                float2 o0 = make_float2(v0, v1);
                float2 o1 = make_float2(v2, v3);
                *(float2*)(c0p + col) = o0;
                *(float2*)(c1p + col) = o1;
                if (DO_STATS) {
                    sumr[2 * mt]     += v0 + v1;
                    sqr [2 * mt]     += v0 * v0 + v1 * v1;
                    sumr[2 * mt + 1] += v2 + v3;
                    sqr [2 * mt + 1] += v2 * v2 + v3 * v3;
                }
            }
        }
    }
    if (DO_STATS) {
        __syncthreads();
        float* sred = (float*)sm;                // reuse smem
        sred[tid] = 0.f; sred[128 + tid] = 0.f;
        __syncthreads();
        #pragma unroll
        for (int i = 0; i < 8; i++) {
            int lr = wr * 64 + (i >> 1) * 16 + g + (i & 1) * 8;
            atomicAdd(&sred[lr], sumr[i]);
            atomicAdd(&sred[128 + lr], sqr[i]);
        }
        __syncthreads();
        atomicAdd(&d_Sum[rowA + tid], sred[tid]);
        atomicAdd(&d_Sq [rowA + tid], sred[128 + tid]);
    }
}

// ---------------- BN finalize / apply ----------------
__global__ void finalize_k(const float* __restrict__ gamma, const float* __restrict__ beta)
{
    int c = threadIdx.x;
    if (c < CIN) {
        const float cnt = (float)((long long)B_ * NPIX);
        float mean = d_Sum[c] / cnt;
        float var  = d_Sq[c] / cnt - mean * mean;
        float s = gamma[c] * rsqrtf(var + EPSV);
        d_Scale[c] = s;
        d_Shift[c] = beta[c] - mean * s;
    }
}

__global__ void apply_k(float* __restrict__ out)
{
    const long long n4 = (long long)B_ * CIN * NPIX / 4;
    const long long stride = (long long)gridDim.x * blockDim.x;
    for (long long i = (long long)blockIdx.x * blockDim.x + threadIdx.x; i < n4; i += stride) {
        int c = (int)((i / (NPIX / 4)) % CIN);
        float s = d_Scale[c], sh = d_Shift[c];
        float4 v = ((float4*)out)[i];
        v.x = v.x * s + sh; v.y = v.y * s + sh;
        v.z = v.z * s + sh; v.w = v.w * s + sh;
        ((float4*)out)[i] = v;
    }
}

// ---------------- launch ----------------
extern "C" void kernel_launch(void* const* d_in, const int* in_sizes, int n_in,
                              void* d_out, int out_size)
{
    const float* x       = (const float*)d_in[0];
    const float* g_w     = (const float*)d_in[1];
    const float* g_b     = (const float*)d_in[2];
    const float* theta_w = (const float*)d_in[3];
    const float* theta_b = (const float*)d_in[4];
    const float* phi_w   = (const float*)d_in[5];
    const float* phi_b   = (const float*)d_in[6];
    const float* W_w     = (const float*)d_in[7];
    const float* W_b     = (const float*)d_in[8];
    const float* gamma   = (const float*)d_in[9];
    const float* beta    = (const float*)d_in[10];
    float* out = (float*)d_out;

    float *tpg, *fbuf, *ybuf, *wcat, *bcat;
    cudaGetSymbolAddress((void**)&tpg,  d_TPG);
    cudaGetSymbolAddress((void**)&fbuf, d_F);
    cudaGetSymbolAddress((void**)&ybuf, d_Y);
    cudaGetSymbolAddress((void**)&wcat, d_Wcat);
    cudaGetSymbolAddress((void**)&bcat, d_Bcat);

    const long long sX   = (long long)CIN * NPIX;
    const long long sTPG = (long long)3 * CI * NPIX;
    const long long sF   = (long long)CI * CI;
    const long long sY   = (long long)CI * NPIX;
    const int nBlk = (NPIX + 127) / 128;                 // 25

    constexpr int SMEM = 2 * 8448 * 4;                   // 67584 B

    cudaFuncSetAttribute(mma_gemm<false, true,  false, false>, cudaFuncAttributeMaxDynamicSharedMemorySize, SMEM);
    cudaFuncSetAttribute(mma_gemm<true,  false, false, false>, cudaFuncAttributeMaxDynamicSharedMemorySize, SMEM);
    cudaFuncSetAttribute(mma_gemm<false, false, false, false>, cudaFuncAttributeMaxDynamicSharedMemorySize, SMEM);
    cudaFuncSetAttribute(mma_gemm<false, true,  true,  true >, cudaFuncAttributeMaxDynamicSharedMemorySize, SMEM);

    // 0) prep
    prep_k<<<(3 * CI * CIN + 255) / 256, 256>>>(g_w, g_b, theta_w, theta_b, phi_w, phi_b);

    // 1) theta|phi|g = Wcat[768,512] @ x[512,3136] + Bcat
    mma_gemm<false, true, false, false><<<dim3(nBlk, 6, B_), 128, SMEM>>>(
        NPIX, CIN / 32, 1.f,
        wcat, CIN, 0,
        x, NPIX, sX,
        tpg, NPIX, sTPG,
        bcat, nullptr, 0);

    // 2) gram: f = theta @ phi^T / N     (B = phi, [Npix-rows=256? no: B rows are n-dim])
    mma_gemm<true, false, false, false><<<dim3(2, 2, B_), 128, SMEM>>>(
        CI, NPIX / 32, 1.f / (float)NPIX,
        tpg, NPIX, sTPG,
        tpg + (long long)CI * NPIX, NPIX, sTPG,
        fbuf, CI, sF,
        nullptr, nullptr, 0);

    // 3) y = f @ g
    mma_gemm<false, false, false, false><<<dim3(nBlk, 2, B_), 128, SMEM>>>(
        NPIX, CI / 32, 1.f,
        fbuf, CI, sF,
        tpg + (long long)2 * CI * NPIX, NPIX, sTPG,
        ybuf, NPIX, sY,
        nullptr, nullptr, 0);

    // 4) z = W_w @ y + W_b + x  (fused BN stats)
    mma_gemm<false, true, true, true><<<dim3(nBlk, 4, B_), 128, SMEM>>>(
        NPIX, CI / 32, 1.f,
        W_w, CI, 0,
        ybuf, NPIX, sY,
        out, NPIX, sX,
        W_b, x, sX);

    // 5) BN finalize + apply
    finalize_k<<<1, 512>>>(gamma, beta);
    apply_k<<<1184, 256>>>(out);
}

// round 7
// speedup vs baseline: 3.1598x; 1.6655x over previous
#include <cuda_runtime.h>
#include <cstdint>

#define B_    32
#define CIN   512
#define CI    256
#define NPIX  3136
#define EPSV  1e-5f

// ---------------- scratch (static device globals; no allocation) ----------------
__device__ float d_TPG[(size_t)B_ * 3 * CI * NPIX];   // [b][768][3136]: theta|phi|g (tf32-rounded)
__device__ float d_F  [(size_t)B_ * CI * CI];         // [b][256][256]  (tf32-rounded)
__device__ float d_Y  [(size_t)B_ * CI * NPIX];       // [b][256][3136] (tf32-rounded)
__device__ float d_Wcat[3 * CI * CIN];                // tf32-rounded
__device__ float d_Wr  [CIN * CI];                    // tf32-rounded W_w
__device__ float d_Bcat[3 * CI];
__device__ float d_Sum[CIN];
__device__ float d_Sq [CIN];
__device__ float d_Scale[CIN];
__device__ float d_Shift[CIN];

// ================= PTX helpers (sm_80+-portable) =================
__device__ __forceinline__ uint32_t smem_u32(const void* p) {
    uint32_t a;
    asm("{ .reg .u64 t; cvta.to.shared.u64 t, %1; cvt.u32.u64 %0, t; }" : "=r"(a) : "l"(p));
    return a;
}
__device__ __forceinline__ void cp16(uint32_t d, const void* s, bool ok) {
    int sz = ok ? 16 : 0;
    asm volatile("cp.async.cg.shared.global [%0], [%1], 16, %2;" :: "r"(d), "l"(s), "r"(sz) : "memory");
}
__device__ __forceinline__ void cp_commit() { asm volatile("cp.async.commit_group;" ::: "memory"); }
__device__ __forceinline__ void cp_wait1()  { asm volatile("cp.async.wait_group 1;" ::: "memory"); }
__device__ __forceinline__ uint32_t f2tf(float f) {
    uint32_t u;
    asm("cvt.rna.tf32.f32 %0, %1;" : "=r"(u) : "f"(f));
    return u;
}
__device__ __forceinline__ float rndf(float f) { return __uint_as_float(f2tf(f)); }
__device__ __forceinline__ void mma8(float* c, const uint32_t* a, const uint32_t* b) {
    asm volatile(
        "mma.sync.aligned.m16n8k8.row.col.f32.tf32.tf32.f32 "
        "{%0,%1,%2,%3}, {%4,%5,%6,%7}, {%8,%9}, {%0,%1,%2,%3};"
        : "+f"(c[0]), "+f"(c[1]), "+f"(c[2]), "+f"(c[3])
        : "r"(a[0]), "r"(a[1]), "r"(a[2]), "r"(a[3]), "r"(b[0]), "r"(b[1]));
}

// ---------------- prep: concat+round weights, zero stats ----------------
__global__ void prep_k(const float* __restrict__ gw, const float* __restrict__ gb,
                       const float* __restrict__ tw, const float* __restrict__ tb,
                       const float* __restrict__ pw, const float* __restrict__ pb,
                       const float* __restrict__ ww)
{
    int i = blockIdx.x * 256 + threadIdx.x;
    const int per = CI * CIN;
    if (i < 3 * per) {
        int m = i / per, off = i - m * per;
        d_Wcat[i] = rndf((m == 0 ? tw : (m == 1 ? pw : gw))[off]);
    }
    if (i < CIN * CI) d_Wr[i] = rndf(ww[i]);
    if (i < CI)            d_Bcat[i] = tb[i];
    else if (i < 2 * CI)   d_Bcat[i] = pb[i - CI];
    else if (i < 3 * CI)   d_Bcat[i] = gb[i - 2 * CI];
    if (i < CIN) { d_Sum[i] = 0.f; d_Sq[i] = 0.f; }
}

// ================= tf32 mma.sync GEMM, 3-stage cp.async pipeline =================
// D[M,Npix] = alpha*A@op(B) (+bias)(+res), fp32 accum.
// A: [M,K] K-contig (pre-rounded tf32).
// B: TRANS_B ? [Npix,K] K-contig (out=A@B^T) : [K,Npix] pix-contig.
// Block 128x128, 256 threads (8 warps, 64x32 warp tiles), KTILE=32.
// Smem/stage (floats): A 128x36, B TRANS? 128x36 : 32x136 (conflict-free pads).
template<bool TRANS_B, bool CVT_B, bool HAS_BIAS, bool HAS_RES, bool DO_STATS, bool ROUND_OUT>
__global__ void __launch_bounds__(256, 2) mma_gemm(
    int Npix, int KT, float alpha,
    const float* __restrict__ A,  int lda, long long sA,
    const float* __restrict__ Bm, int ldb, long long sB,
    float* __restrict__ C,        int ldc, long long sC,
    const float* __restrict__ bias,
    const float* __restrict__ res, long long sR)
{
    constexpr int ASZ = 128 * 36;                    // 4608 floats
    constexpr int BSZ = TRANS_B ? 128 * 36 : 32 * 136;
    constexpr int STG = ASZ + BSZ;
    extern __shared__ uint32_t sm[];
    const uint32_t smb = smem_u32(sm);

    const int tid = threadIdx.x;
    const int bz = blockIdx.z;
    A  += (long long)bz * sA;
    Bm += (long long)bz * sB;
    C  += (long long)bz * sC;
    const int rowA = blockIdx.y * 128;
    const int colB = blockIdx.x * 128;
    const int warp = tid >> 5, lane = tid & 31;
    const int wr = warp >> 2, wc = warp & 3;         // 2x4 warp grid, 64x32 tiles
    const int g = lane >> 2, q = lane & 3;

    float acc[4][4][4];
    #pragma unroll
    for (int i = 0; i < 4; i++)
        #pragma unroll
        for (int j = 0; j < 4; j++)
            #pragma unroll
            for (int k = 0; k < 4; k++) acc[i][j][k] = 0.f;

    auto load_tile = [&](int s, int kt) {
        const uint32_t baseA = smb + (uint32_t)(s * STG) * 4;
        #pragma unroll
        for (int j = 0; j < 4; j++) {                // A: 1024 16B chunks
            int u = tid + j * 256;
            int row = u >> 3, k16 = u & 7;
            cp16(baseA + (uint32_t)(row * 36 + k16 * 4) * 4,
                 A + (long long)(rowA + row) * lda + kt * 32 + k16 * 4, true);
        }
        const uint32_t baseB = baseA + ASZ * 4;
        #pragma unroll
        for (int j = 0; j < 4; j++) {                // B: 1024 16B chunks
            int u = tid + j * 256;
            if (TRANS_B) {
                int row = u >> 3, k16 = u & 7;
                bool ok = colB + row < Npix;
                cp16(baseB + (uint32_t)(row * 36 + k16 * 4) * 4,
                     Bm + (long long)(ok ? colB + row : 0) * ldb + kt * 32 + k16 * 4, ok);
            } else {
                int k = u >> 5, n16 = u & 31;
                int col = colB + n16 * 4;
                bool ok = col < Npix;
                cp16(baseB + (uint32_t)(k * 136 + n16 * 4) * 4,
                     Bm + (long long)(kt * 32 + k) * ldb + (ok ? col : 0), ok);
            }
        }
        cp_commit();
    };

    auto compute = [&](int s) {
        const uint32_t* As_ = sm + s * STG;
        const uint32_t* Bs_ = As_ + ASZ;
        #pragma unroll
        for (int k8 = 0; k8 < 4; k8++) {
            const int kb = k8 * 8;
            uint32_t af[4][4], bf[4][2];
            #pragma unroll
            for (int mt = 0; mt < 4; mt++) {
                int m0 = wr * 64 + mt * 16 + g;
                af[mt][0] = As_[m0 * 36 + kb + q];
                af[mt][1] = As_[(m0 + 8) * 36 + kb + q];
                af[mt][2] = As_[m0 * 36 + kb + q + 4];
                af[mt][3] = As_[(m0 + 8) * 36 + kb + q + 4];
            }
            #pragma unroll
            for (int nt = 0; nt < 4; nt++) {
                int n0 = wc * 32 + nt * 8 + g;
                uint32_t b0, b1;
                if (TRANS_B) {
                    b0 = Bs_[n0 * 36 + kb + q];
                    b1 = Bs_[n0 * 36 + kb + q + 4];
                } else {
                    b0 = Bs_[(kb + q) * 136 + n0];
                    b1 = Bs_[(kb + q + 4) * 136 + n0];
                }
                if (CVT_B) {
                    b0 = f2tf(__uint_as_float(b0));
                    b1 = f2tf(__uint_as_float(b1));
                }
                bf[nt][0] = b0; bf[nt][1] = b1;
            }
            #pragma unroll
            for (int mt = 0; mt < 4; mt++)
                #pragma unroll
                for (int nt = 0; nt < 4; nt++)
                    mma8(acc[mt][nt], af[mt], bf[nt]);
        }
    };

    // prologue: tiles 0,1 -> stages 0,1
    load_tile(0, 0);
    load_tile(1, 1);

    for (int kt = 0; kt < KT; kt++) {
        cp_wait1();                                  // tile kt resident
        __syncthreads();
        int lt = kt + 2;
        if (lt < KT) load_tile(lt % 3, lt);          // fills stage (kt-1)%3
        else cp_commit();                            // keep group count uniform
        compute(kt % 3);
    }

    // ---------------- epilogue ----------------
    float sumr[8], sqr[8];
    if (DO_STATS)
        #pragma unroll
        for (int i = 0; i < 8; i++) { sumr[i] = 0.f; sqr[i] = 0.f; }

    #pragma unroll
    for (int mt = 0; mt < 4; mt++) {
        const int r0 = rowA + wr * 64 + mt * 16 + g;
        const int r1 = r0 + 8;
        const float bv0 = HAS_BIAS ? bias[r0] : 0.f;
        const float bv1 = HAS_BIAS ? bias[r1] : 0.f;
        float* c0p = C + (long long)r0 * ldc;
        float* c1p = C + (long long)r1 * ldc;
        const float* rr0 = HAS_RES ? (res + (long long)bz * sR + (long long)r0 * ldc) : nullptr;
        const float* rr1 = HAS_RES ? (res + (long long)bz * sR + (long long)r1 * ldc) : nullptr;
        #pragma unroll
        for (int nt = 0; nt < 4; nt++) {
            const int col = colB + wc * 32 + nt * 8 + q * 2;
            if (col < Npix) {
                float v0 = acc[mt][nt][0] * alpha + bv0;
                float v1 = acc[mt][nt][1] * alpha + bv0;
                float v2 = acc[mt][nt][2] * alpha + bv1;
                float v3 = acc[mt][nt][3] * alpha + bv1;
                if (HAS_RES) {
                    float2 e0 = *(const float2*)(rr0 + col);
                    float2 e1 = *(const float2*)(rr1 + col);
                    v0 += e0.x; v1 += e0.y; v2 += e1.x; v3 += e1.y;
                }
                if (DO_STATS) {
                    sumr[2 * mt]     += v0 + v1;
                    sqr [2 * mt]     += v0 * v0 + v1 * v1;
                    sumr[2 * mt + 1] += v2 + v3;
                    sqr [2 * mt + 1] += v2 * v2 + v3 * v3;
                }
                if (ROUND_OUT) {
                    v0 = rndf(v0); v1 = rndf(v1); v2 = rndf(v2); v3 = rndf(v3);
                }
                *(float2*)(c0p + col) = make_float2(v0, v1);
                *(float2*)(c1p + col) = make_float2(v2, v3);
            }
        }
    }
    if (DO_STATS) {
        __syncthreads();
        float* sred = (float*)sm;
        if (tid < 128) { sred[tid] = 0.f; sred[128 + tid] = 0.f; }
        __syncthreads();
        #pragma unroll
        for (int i = 0; i < 8; i++) {
            int lr = wr * 64 + (i >> 1) * 16 + g + (i & 1) * 8;
            atomicAdd(&sred[lr], sumr[i]);
            atomicAdd(&sred[128 + lr], sqr[i]);
        }
        __syncthreads();
        if (tid < 128) {
            atomicAdd(&d_Sum[rowA + tid], sred[tid]);
            atomicAdd(&d_Sq [rowA + tid], sred[128 + tid]);
        }
    }
}

// ---------------- BN finalize / apply ----------------
__global__ void finalize_k(const float* __restrict__ gamma, const float* __restrict__ beta)
{
    int c = threadIdx.x;
    if (c < CIN) {
        const float cnt = (float)((long long)B_ * NPIX);
        float mean = d_Sum[c] / cnt;
        float var  = d_Sq[c] / cnt - mean * mean;
        float s = gamma[c] * rsqrtf(var + EPSV);
        d_Scale[c] = s;
        d_Shift[c] = beta[c] - mean * s;
    }
}

__global__ void apply_k(float* __restrict__ out)
{
    const long long n4 = (long long)B_ * CIN * NPIX / 4;
    const long long stride = (long long)gridDim.x * blockDim.x;
    for (long long i = (long long)blockIdx.x * blockDim.x + threadIdx.x; i < n4; i += stride) {
        int c = (int)((i / (NPIX / 4)) % CIN);
        float s = d_Scale[c], sh = d_Shift[c];
        float4 v = ((float4*)out)[i];
        v.x = v.x * s + sh; v.y = v.y * s + sh;
        v.z = v.z * s + sh; v.w = v.w * s + sh;
        ((float4*)out)[i] = v;
    }
}

// ---------------- launch ----------------
extern "C" void kernel_launch(void* const* d_in, const int* in_sizes, int n_in,
                              void* d_out, int out_size)
{
    const float* x       = (const float*)d_in[0];
    const float* g_w     = (const float*)d_in[1];
    const float* g_b     = (const float*)d_in[2];
    const float* theta_w = (const float*)d_in[3];
    const float* theta_b = (const float*)d_in[4];
    const float* phi_w   = (const float*)d_in[5];
    const float* phi_b   = (const float*)d_in[6];
    const float* W_w     = (const float*)d_in[7];
    const float* W_b     = (const float*)d_in[8];
    const float* gamma   = (const float*)d_in[9];
    const float* beta    = (const float*)d_in[10];
    float* out = (float*)d_out;

    float *tpg, *fbuf, *ybuf, *wcat, *bcat, *wr;
    cudaGetSymbolAddress((void**)&tpg,  d_TPG);
    cudaGetSymbolAddress((void**)&fbuf, d_F);
    cudaGetSymbolAddress((void**)&ybuf, d_Y);
    cudaGetSymbolAddress((void**)&wcat, d_Wcat);
    cudaGetSymbolAddress((void**)&bcat, d_Bcat);
    cudaGetSymbolAddress((void**)&wr,   d_Wr);

    const long long sX   = (long long)CIN * NPIX;
    const long long sTPG = (long long)3 * CI * NPIX;
    const long long sF   = (long long)CI * CI;
    const long long sY   = (long long)CI * NPIX;
    const int nBlk = (NPIX + 127) / 128;             // 25

    constexpr int STG_N = (128 * 36 + 32 * 136) * 4; // 35840 B
    constexpr int STG_T = (128 * 36 + 128 * 36) * 4; // 36864 B
    constexpr int SMEM_N = 3 * STG_N;                // 107520
    constexpr int SMEM_T = 3 * STG_T;                // 110592

    cudaFuncSetAttribute(mma_gemm<false, true,  true,  false, false, true >, cudaFuncAttributeMaxDynamicSharedMemorySize, SMEM_N);
    cudaFuncSetAttribute(mma_gemm<true,  false, false, false, false, true >, cudaFuncAttributeMaxDynamicSharedMemorySize, SMEM_T);
    cudaFuncSetAttribute(mma_gemm<false, false, false, false, false, true >, cudaFuncAttributeMaxDynamicSharedMemorySize, SMEM_N);
    cudaFuncSetAttribute(mma_gemm<false, false, true,  true,  true,  false>, cudaFuncAttributeMaxDynamicSharedMemorySize, SMEM_N);

    // 0) prep
    prep_k<<<(3 * CI * CIN + 255) / 256, 256>>>(g_w, g_b, theta_w, theta_b, phi_w, phi_b, W_w);

    // 1) theta|phi|g = Wcat[768,512] @ x[512,3136] + Bcat  (x unrounded -> CVT_B)
    mma_gemm<false, true, true, false, false, true><<<dim3(nBlk, 6, B_), 256, SMEM_N>>>(
        NPIX, CIN / 32, 1.f,
        wcat, CIN, 0,
        x, NPIX, sX,
        tpg, NPIX, sTPG,
        bcat, nullptr, 0);

    // 2) gram: f = theta @ phi^T / N   (both pre-rounded)
    mma_gemm<true, false, false, false, false, true><<<dim3(2, 2, B_), 256, SMEM_T>>>(
        CI, NPIX / 32, 1.f / (float)NPIX,
        tpg, NPIX, sTPG,
        tpg + (long long)CI * NPIX, NPIX, sTPG,
        fbuf, CI, sF,
        nullptr, nullptr, 0);

    // 3) y = f @ g  (both pre-rounded)
    mma_gemm<false, false, false, false, false, true><<<dim3(nBlk, 2, B_), 256, SMEM_N>>>(
        NPIX, CI / 32, 1.f,
        fbuf, CI, sF,
        tpg + (long long)2 * CI * NPIX, NPIX, sTPG,
        ybuf, NPIX, sY,
        nullptr, nullptr, 0);

    // 4) z = Wr @ y + W_b + x  (fused BN stats; full-precision output)
    mma_gemm<false, false, true, true, true, false><<<dim3(nBlk, 4, B_), 256, SMEM_N>>>(
        NPIX, CI / 32, 1.f,
        wr, CI, 0,
        ybuf, NPIX, sY,
        out, NPIX, sX,
        W_b, x, sX);

    // 5) BN finalize + apply
    finalize_k<<<1, 512>>>(gamma, beta);
    apply_k<<<1184, 256>>>(out);
}